// round 10
// baseline (speedup 1.0000x reference)
#include <cuda_runtime.h>
#include <math.h>

#define NB 16
#define NC 256
#define PLANE 3136
#define NPLANES 4096
typedef unsigned long long ull;

// scratch (static device globals; no allocation)
__device__ float g_xfuse[NPLANES * PLANE];   // 51.4 MB
__device__ float g_pooled[NB * 49 * NC];     // [B][pos][C]
__device__ float g_h[NB * 50 * 64];          // hidden layer (pos 49 = mean)
__device__ float g_wdyn[NB * 49 * NC];       // [B][pos][C]
__device__ float g_bdyn[NB * NC];            // [B][C]
__device__ float g_pw1T[256 * 64];           // [k][o]
__device__ float g_pw2T[64 * 1024];          // [k][oc]
__device__ float g_w1T[49 * 1024];           // [pos][g*C+c]

__device__ __forceinline__ void ffma2(ull& d, ull a, ull b) {
    asm("fma.rn.f32x2 %0, %1, %2, %0;" : "+l"(d) : "l"(a), "l"(b));
}
__device__ __forceinline__ float2 u2f2(ull v) {
    float2 r;
    r.x = __uint_as_float((unsigned)v);
    r.y = __uint_as_float((unsigned)(v >> 32));
    return r;
}

// ---------------------------------------------------------------------------
// Kernel 1: fused dw3x3+BN (x2), relu6 gate, x_fuse, 7x7 block-mean pool.
// warp = column-group, lane = row -> conflict-free LDS.64; S-accumulators
// for the odd tap (no po recombines). 14 warps/block -> 2 blocks resident
// max, so allow 72 regs via launch_bounds(448,2).
// Blocks >= NPLANES instead perform the small weight transposes.
// ---------------------------------------------------------------------------
__global__ __launch_bounds__(448, 2) void k_fuse(
    const float* __restrict__ x1,
    const float* __restrict__ dw1_w, const float* __restrict__ dw1_g,
    const float* __restrict__ dw1_b, const float* __restrict__ dw1_m,
    const float* __restrict__ dw1_v,
    const float* __restrict__ dw2_w, const float* __restrict__ dw2_g,
    const float* __restrict__ dw2_b, const float* __restrict__ dw2_m,
    const float* __restrict__ dw2_v,
    const float* __restrict__ pw1, const float* __restrict__ pw2,
    const float* __restrict__ w1grp) {
    const int tid = threadIdx.x;

    if (blockIdx.x >= NPLANES) {           // transpose side-work
        int i = (blockIdx.x - NPLANES) * 448 + tid;
        if (i < 16384) {                   // pw1 [64,256] -> [256,64]
            int k = i >> 6, o = i & 63;
            g_pw1T[i] = pw1[o * 256 + k];
        } else if (i < 81920) {            // pw2 [1024,64] -> [64,1024]
            int j = i - 16384;
            int k = j >> 10, oc = j & 1023;
            g_pw2T[j] = pw2[oc * 64 + k];
        } else if (i < 132096) {           // weight1 [G*C,49] -> [49,G*C]
            int l = i - 81920;
            int pos = l / 1024, gc = l & 1023;
            g_w1T[l] = w1grp[gc * 49 + pos];
        }
        return;
    }

    __shared__ float s[58 * 66];           // tile, halo 1, stride 66
    __shared__ float2 sw1[9], sw2[9];      // packed (w,w) weights
    __shared__ float partial[392];

    const int blk = blockIdx.x;
    const int b = blk >> 8, c = blk & 255;

    // halo zeroing (rows 0,57 x 0..57; rows 1..56 x in {0,57}): 228 cells
    if (tid < 228) {
        int r, x;
        if (tid < 116) {
            r = (tid < 58) ? 0 : 57;
            x = (tid < 58) ? tid : tid - 58;
        } else {
            int j = tid - 116;
            r = 1 + (j >> 1);
            x = (j & 1) ? 57 : 0;
        }
        s[r * 66 + x] = 0.f;
    }
    {
        const float4* __restrict__ xp4 =
            (const float4*)(x1 + (size_t)blk * PLANE);
        for (int idx = tid; idx < 784; idx += 448) {
            int r = idx / 14, c4 = idx - r * 14;
            float4 v = xp4[idx];
            float* d = &s[(r + 1) * 66 + 1 + c4 * 4];
            d[0] = v.x; d[1] = v.y; d[2] = v.z; d[3] = v.w;
        }
    }
    // BN-folded channel scalars
    const float s1 = dw1_g[c] * rsqrtf(dw1_v[c] + 1e-5f);
    const float s2 = dw2_g[c] * rsqrtf(dw2_v[c] + 1e-5f);
    const float bb1 = dw1_b[c] - dw1_m[c] * s1;
    const float bb2 = dw2_b[c] - dw2_m[c] * s2;
    if (tid < 9) {
        float wa = dw1_w[c * 9 + tid] * s1;
        float wb = dw2_w[c * 9 + tid] * s2;
        sw1[tid] = make_float2(wa, wa);
        sw2[tid] = make_float2(wb, wb);
    }
    __syncthreads();

    const int wp = tid >> 5, lane = tid & 31;
    const int band = (wp >= 7) ? 1 : 0;
    const int cg = wp - band * 7;
    const int row = band * 32 + lane;

    if (row < 56) {
        ull aA[4] = {0, 0, 0, 0}, aB[4] = {0, 0, 0, 0};
        ull SA[5] = {0, 0, 0, 0, 0}, SB[5] = {0, 0, 0, 0, 0};
#pragma unroll
        for (int ky = 0; ky < 3; ky++) {
            const float* rp = &s[(row + ky) * 66 + cg * 8];
            ull pe[5];
#pragma unroll
            for (int k = 0; k < 5; k++) pe[k] = *(const ull*)(rp + 2 * k);
#pragma unroll
            for (int t = 0; t < 2; t++) {   // even taps kx = 0, 2
                ull wa = *(const ull*)&sw1[ky * 3 + 2 * t];
                ull wb = *(const ull*)&sw2[ky * 3 + 2 * t];
#pragma unroll
                for (int j = 0; j < 4; j++) {
                    ffma2(aA[j], wa, pe[j + t]);
                    ffma2(aB[j], wb, pe[j + t]);
                }
            }
            {                               // odd tap kx = 1 -> S
                ull wa = *(const ull*)&sw1[ky * 3 + 1];
                ull wb = *(const ull*)&sw2[ky * 3 + 1];
#pragma unroll
                for (int i = 0; i < 5; i++) {
                    ffma2(SA[i], wa, pe[i]);
                    ffma2(SB[i], wb, pe[i]);
                }
            }
        }
        float f[8];
        float rsum = 0.f;
#pragma unroll
        for (int j = 0; j < 4; j++) {
            float2 pa = u2f2(aA[j]), pb = u2f2(aB[j]);
            float2 qa0 = u2f2(SA[j]), qa1 = u2f2(SA[j + 1]);
            float2 qb0 = u2f2(SB[j]), qb1 = u2f2(SB[j + 1]);
            float c10 = pa.x + qa0.y, c11 = pa.y + qa1.x;
            float c20 = pb.x + qb0.y, c21 = pb.y + qb1.x;
            float a0 = fminf(fmaxf(c10 + bb1, 0.f), 6.f);
            float a1 = fminf(fmaxf(c11 + bb1, 0.f), 6.f);
            float v0 = a0 * (c20 + bb2);
            float v1 = a1 * (c21 + bb2);
            f[2 * j] = v0; f[2 * j + 1] = v1;
            rsum += v0 + v1;
        }
        float4* op = (float4*)(g_xfuse + (size_t)blk * PLANE + row * 56 + cg * 8);
        op[0] = make_float4(f[0], f[1], f[2], f[3]);
        op[1] = make_float4(f[4], f[5], f[6], f[7]);
        partial[row * 7 + cg] = rsum;
    }
    __syncthreads();

    if (tid < 49) {
        const int pr = tid / 7, pc = tid - pr * 7;
        float sm = 0.f;
#pragma unroll
        for (int i = 0; i < 8; i++) sm += partial[(pr * 8 + i) * 7 + pc];
        g_pooled[(b * 49 + tid) * NC + c] = sm * (1.f / 64.f);
    }
}

// ---------------------------------------------------------------------------
// Kernel 2a: hidden layer h = gelu(pw1 @ v + pb1) for all (b, pos).
// ---------------------------------------------------------------------------
__global__ __launch_bounds__(256) void k_dyn_h(const float* __restrict__ pb1) {
    __shared__ float v[10 * 256];

    const int pg = blockIdx.x, b = blockIdx.y, t = threadIdx.x;
    const int base = pg * 10;
    const int nload = (pg == 4) ? 9 : 10;

    for (int i = t; i < nload * 256; i += 256)
        v[i] = g_pooled[(b * 49 + base) * NC + i];
    if (pg == 4) {
        float sm = 0.f;
        for (int p = 0; p < 49; p++) sm += g_pooled[(b * 49 + p) * NC + t];
        v[9 * 256 + t] = sm * (1.f / 49.f);
    }
    __syncthreads();

    const int o = t & 63;
    for (int pl = t >> 6; pl < 10; pl += 4) {
        const float* vr = &v[pl * 256];
        float acc0 = 0.f, acc1 = 0.f;
#pragma unroll 8
        for (int k = 0; k < 256; k += 2) {
            acc0 += g_pw1T[k * 64 + o] * vr[k];
            acc1 += g_pw1T[(k + 1) * 64 + o] * vr[k + 1];
        }
        float x = acc0 + acc1 + pb1[o];
        g_h[(b * 50 + base + pl) * 64 + o] =
            0.5f * x * (1.f + erff(x * 0.70710678118654752f));
    }
}

// ---------------------------------------------------------------------------
// Kernel 2b: logits = h @ pw2 (+pb2), softmax over G, weighted sums.
// ---------------------------------------------------------------------------
__global__ __launch_bounds__(256) void k_dyn2(
    const float* __restrict__ pb2, const float* __restrict__ bias1) {
    __shared__ float hs[50 * 64];

    const int b = blockIdx.y, t = threadIdx.x;
    const int c = blockIdx.x * 32 + (t & 31);
    const int ps = t >> 5;                 // 0..7 pos stripe

    for (int i = t; i < 3200; i += 256) hs[i] = g_h[b * 3200 + i];
    __syncthreads();

    const int np = (ps < 2) ? 7 : 6;       // positions ps, ps+8, ...
    float acc[7][4];
#pragma unroll
    for (int i = 0; i < 7; i++)
#pragma unroll
        for (int g = 0; g < 4; g++) acc[i][g] = 0.f;

#pragma unroll 4
    for (int k = 0; k < 64; k++) {
        const float w0 = g_pw2T[k * 1024 + c];
        const float w1 = g_pw2T[k * 1024 + 256 + c];
        const float w2 = g_pw2T[k * 1024 + 512 + c];
        const float w3 = g_pw2T[k * 1024 + 768 + c];
#pragma unroll
        for (int i = 0; i < 7; i++) {
            if (i < np) {
                const float h = hs[(ps + 8 * i) * 64 + k];
                acc[i][0] += h * w0;
                acc[i][1] += h * w1;
                acc[i][2] += h * w2;
                acc[i][3] += h * w3;
            }
        }
    }

    const float q0 = pb2[c], q1 = pb2[256 + c], q2 = pb2[512 + c], q3 = pb2[768 + c];
#pragma unroll
    for (int i = 0; i < 7; i++) {
        if (i >= np) break;
        const int pos = ps + 8 * i;
        float l0 = acc[i][0] + q0, l1 = acc[i][1] + q1;
        float l2 = acc[i][2] + q2, l3 = acc[i][3] + q3;
        float m = fmaxf(fmaxf(l0, l1), fmaxf(l2, l3));
        float e0 = expf(l0 - m), e1 = expf(l1 - m);
        float e2 = expf(l2 - m), e3 = expf(l3 - m);
        float inv = 1.f / (e0 + e1 + e2 + e3);
        if (pos < 49) {
            const float* wp = &g_w1T[pos * 1024];
            float wv = e0 * wp[c] + e1 * wp[256 + c] + e2 * wp[512 + c] +
                       e3 * wp[768 + c];
            g_wdyn[(b * 49 + pos) * NC + c] = wv * inv;
        } else {
            float bv = e0 * bias1[c] + e1 * bias1[256 + c] +
                       e2 * bias1[512 + c] + e3 * bias1[768 + c];
            g_bdyn[b * NC + c] = bv * inv;
        }
    }
}

// ---------------------------------------------------------------------------
// Kernel 3: dynamic 7x7 depthwise conv + dynamic bias.
// warp = column-group, lane = row -> conflict-free LDS.64; shifted
// S-accumulators for odd taps. launch_bounds(448,2): 14-warp blocks cap at
// 2 resident anyway, so give ptxas the full 72-reg budget for scheduling.
// ---------------------------------------------------------------------------
__global__ __launch_bounds__(448, 2) void k_conv(float* __restrict__ out) {
    __shared__ float s[62 * 66];           // tile, halo 3, stride 66
    __shared__ float2 wsm2[49];            // packed (w,w)
    __shared__ float bsm;

    const int blk = blockIdx.x;
    const int b = blk >> 8, c = blk & 255;
    const int tid = threadIdx.x;

    // halo zeroing: 708 cells over 448 threads
    for (int i = tid; i < 708; i += 448) {
        int r, x;
        if (i < 372) {
            int rr = i / 62; x = i - rr * 62;
            r = (rr < 3) ? rr : 56 + rr;
        } else {
            int j = i - 372;
            r = 3 + j / 6;
            int xs = j - (j / 6) * 6;
            x = (xs < 3) ? xs : 56 + xs;
        }
        s[r * 66 + x] = 0.f;
    }
    {
        const float4* __restrict__ xp4 =
            (const float4*)(g_xfuse + (size_t)blk * PLANE);
        for (int idx = tid; idx < 784; idx += 448) {
            int r = idx / 14, c4 = idx - r * 14;
            float4 v = xp4[idx];
            float* d = &s[(r + 3) * 66 + 3 + c4 * 4];
            d[0] = v.x; d[1] = v.y; d[2] = v.z; d[3] = v.w;
        }
    }
    if (tid < 49) {
        float w = g_wdyn[(b * 49 + tid) * NC + c];
        wsm2[tid] = make_float2(w, w);
    }
    if (tid == 63) bsm = g_bdyn[b * NC + c];
    __syncthreads();

    const int wp = tid >> 5, lane = tid & 31;
    const int band = (wp >= 7) ? 1 : 0;
    const int cg = wp - band * 7;
    const int row = band * 32 + lane;

    if (row < 56) {
        ull acc[4] = {0, 0, 0, 0};
        ull S[5] = {0, 0, 0, 0, 0};
#pragma unroll
        for (int ky = 0; ky < 7; ky++) {
            const float* rp = &s[(row + ky) * 66 + cg * 8];
            ull pe[7];
#pragma unroll
            for (int k = 0; k < 7; k++) pe[k] = *(const ull*)(rp + 2 * k);
#pragma unroll
            for (int t = 0; t < 4; t++) {   // even taps kx = 0,2,4,6
                ull w = *(const ull*)&wsm2[ky * 7 + 2 * t];
#pragma unroll
                for (int j = 0; j < 4; j++) ffma2(acc[j], w, pe[j + t]);
            }
#pragma unroll
            for (int t = 0; t < 3; t++) {   // odd taps kx = 1,3,5 -> S[i]
                ull w = *(const ull*)&wsm2[ky * 7 + 2 * t + 1];
#pragma unroll
                for (int i = 0; i < 5; i++) ffma2(S[i], w, pe[i + t]);
            }
        }
        const float bv = bsm;
        float2 a0 = u2f2(acc[0]), a1 = u2f2(acc[1]);
        float2 a2 = u2f2(acc[2]), a3 = u2f2(acc[3]);
        float2 s0 = u2f2(S[0]), s1 = u2f2(S[1]), s2 = u2f2(S[2]);
        float2 s3 = u2f2(S[3]), s4 = u2f2(S[4]);
        float4* op = (float4*)(out + (size_t)blk * PLANE + row * 56 + cg * 8);
        op[0] = make_float4(a0.x + s0.y + bv, a0.y + s1.x + bv,
                            a1.x + s1.y + bv, a1.y + s2.x + bv);
        op[1] = make_float4(a2.x + s2.y + bv, a2.y + s3.x + bv,
                            a3.x + s3.y + bv, a3.y + s4.x + bv);
    }
}

// ---------------------------------------------------------------------------
extern "C" void kernel_launch(void* const* d_in, const int* in_sizes, int n_in,
                              void* d_out, int out_size) {
    const float* x1    = (const float*)d_in[0];
    const float* dw1_w = (const float*)d_in[1];
    const float* dw1_g = (const float*)d_in[2];
    const float* dw1_b = (const float*)d_in[3];
    const float* dw1_m = (const float*)d_in[4];
    const float* dw1_v = (const float*)d_in[5];
    const float* dw2_w = (const float*)d_in[6];
    const float* dw2_g = (const float*)d_in[7];
    const float* dw2_b = (const float*)d_in[8];
    const float* dw2_m = (const float*)d_in[9];
    const float* dw2_v = (const float*)d_in[10];
    const float* weight1 = (const float*)d_in[11];
    const float* bias1   = (const float*)d_in[12];
    const float* pw1 = (const float*)d_in[13];
    const float* pb1 = (const float*)d_in[14];
    const float* pw2 = (const float*)d_in[15];
    const float* pb2 = (const float*)d_in[16];
    float* out = (float*)d_out;

    k_fuse<<<NPLANES + 295, 448>>>(x1, dw1_w, dw1_g, dw1_b, dw1_m, dw1_v,
                                   dw2_w, dw2_g, dw2_b, dw2_m, dw2_v,
                                   pw1, pw2, weight1);
    k_dyn_h<<<dim3(5, NB), 256>>>(pb1);
    k_dyn2<<<dim3(8, NB), 256>>>(pb2, bias1);
    k_conv<<<NPLANES, 448>>>(out);
}

// round 11
// speedup vs baseline: 1.0967x; 1.0967x over previous
#include <cuda_runtime.h>
#include <math.h>

#define NB 16
#define NC 256
#define PLANE 3136
#define NPLANES 4096
typedef unsigned long long ull;

// scratch (static device globals; no allocation)
__device__ float g_xfuse[NPLANES * PLANE];   // 51.4 MB
__device__ float g_pooled[NB * 49 * NC];     // [B][pos][C]
__device__ float g_h[NB * 50 * 64];          // hidden layer (pos 49 = mean)
__device__ float g_wdyn[NB * 49 * NC];       // [B][pos][C]
__device__ float g_bdyn[NB * NC];            // [B][C]
__device__ float g_pw1T[256 * 64];           // [k][o]
__device__ float g_pw2T[64 * 1024];          // [k][oc]
__device__ float g_w1T[49 * 1024];           // [pos][g*C+c]

__device__ __forceinline__ void ffma2(ull& d, ull a, ull b) {
    asm("fma.rn.f32x2 %0, %1, %2, %0;" : "+l"(d) : "l"(a), "l"(b));
}
__device__ __forceinline__ float2 u2f2(ull v) {
    float2 r;
    r.x = __uint_as_float((unsigned)v);
    r.y = __uint_as_float((unsigned)(v >> 32));
    return r;
}

// ---------------------------------------------------------------------------
// Kernel 1: fused dw3x3+BN (x2), relu6 gate, x_fuse, 7x7 block-mean pool.
// warp = column-group, lane = row -> conflict-free LDS.64 (R9-benched form).
// Blocks >= NPLANES instead perform the small weight transposes.
// ---------------------------------------------------------------------------
__global__ __launch_bounds__(448, 3) void k_fuse(
    const float* __restrict__ x1,
    const float* __restrict__ dw1_w, const float* __restrict__ dw1_g,
    const float* __restrict__ dw1_b, const float* __restrict__ dw1_m,
    const float* __restrict__ dw1_v,
    const float* __restrict__ dw2_w, const float* __restrict__ dw2_g,
    const float* __restrict__ dw2_b, const float* __restrict__ dw2_m,
    const float* __restrict__ dw2_v,
    const float* __restrict__ pw1, const float* __restrict__ pw2,
    const float* __restrict__ w1grp) {
    const int tid = threadIdx.x;

    if (blockIdx.x >= NPLANES) {           // transpose side-work
        int i = (blockIdx.x - NPLANES) * 448 + tid;
        if (i < 16384) {                   // pw1 [64,256] -> [256,64]
            int k = i >> 6, o = i & 63;
            g_pw1T[i] = pw1[o * 256 + k];
        } else if (i < 81920) {            // pw2 [1024,64] -> [64,1024]
            int j = i - 16384;
            int k = j >> 10, oc = j & 1023;
            g_pw2T[j] = pw2[oc * 64 + k];
        } else if (i < 132096) {           // weight1 [G*C,49] -> [49,G*C]
            int l = i - 81920;
            int pos = l / 1024, gc = l & 1023;
            g_w1T[l] = w1grp[gc * 49 + pos];
        }
        return;
    }

    __shared__ float s[58 * 66];           // tile, halo 1, stride 66
    __shared__ float2 sw1[9], sw2[9];      // packed (w,w) weights
    __shared__ float partial[392];

    const int blk = blockIdx.x;
    const int b = blk >> 8, c = blk & 255;

    // halo zeroing (rows 0,57 x 0..57; rows 1..56 x in {0,57}): 228 cells
    if (tid < 228) {
        int r, x;
        if (tid < 116) {
            r = (tid < 58) ? 0 : 57;
            x = (tid < 58) ? tid : tid - 58;
        } else {
            int j = tid - 116;
            r = 1 + (j >> 1);
            x = (j & 1) ? 57 : 0;
        }
        s[r * 66 + x] = 0.f;
    }
    {
        const float4* __restrict__ xp4 =
            (const float4*)(x1 + (size_t)blk * PLANE);
        for (int idx = tid; idx < 784; idx += 448) {
            int r = idx / 14, c4 = idx - r * 14;
            float4 v = xp4[idx];
            float* d = &s[(r + 1) * 66 + 1 + c4 * 4];
            d[0] = v.x; d[1] = v.y; d[2] = v.z; d[3] = v.w;
        }
    }
    // BN-folded channel scalars
    const float s1 = dw1_g[c] * rsqrtf(dw1_v[c] + 1e-5f);
    const float s2 = dw2_g[c] * rsqrtf(dw2_v[c] + 1e-5f);
    const float bb1 = dw1_b[c] - dw1_m[c] * s1;
    const float bb2 = dw2_b[c] - dw2_m[c] * s2;
    if (tid < 9) {
        float wa = dw1_w[c * 9 + tid] * s1;
        float wb = dw2_w[c * 9 + tid] * s2;
        sw1[tid] = make_float2(wa, wa);
        sw2[tid] = make_float2(wb, wb);
    }
    __syncthreads();

    const int wp = tid >> 5, lane = tid & 31;
    const int band = (wp >= 7) ? 1 : 0;
    const int cg = wp - band * 7;
    const int row = band * 32 + lane;

    if (row < 56) {
        ull aA[4] = {0, 0, 0, 0}, aB[4] = {0, 0, 0, 0};
#pragma unroll
        for (int ky = 0; ky < 3; ky++) {
            const float* rp = &s[(row + ky) * 66 + cg * 8];
            ull pe[5];
#pragma unroll
            for (int k = 0; k < 5; k++) pe[k] = *(const ull*)(rp + 2 * k);
            ull po[4];
#pragma unroll
            for (int m = 0; m < 4; m++)
                po[m] = (pe[m] >> 32) | (pe[m + 1] << 32);
#pragma unroll
            for (int t = 0; t < 2; t++) {   // kx = 0, 2
                ull wa = *(const ull*)&sw1[ky * 3 + 2 * t];
                ull wb = *(const ull*)&sw2[ky * 3 + 2 * t];
#pragma unroll
                for (int j = 0; j < 4; j++) {
                    ffma2(aA[j], wa, pe[j + t]);
                    ffma2(aB[j], wb, pe[j + t]);
                }
            }
            {                               // kx = 1
                ull wa = *(const ull*)&sw1[ky * 3 + 1];
                ull wb = *(const ull*)&sw2[ky * 3 + 1];
#pragma unroll
                for (int j = 0; j < 4; j++) {
                    ffma2(aA[j], wa, po[j]);
                    ffma2(aB[j], wb, po[j]);
                }
            }
        }
        float f[8];
        float rsum = 0.f;
#pragma unroll
        for (int j = 0; j < 4; j++) {
            float2 pa = u2f2(aA[j]), pb = u2f2(aB[j]);
            float a0 = fminf(fmaxf(pa.x + bb1, 0.f), 6.f);
            float a1 = fminf(fmaxf(pa.y + bb1, 0.f), 6.f);
            float v0 = a0 * (pb.x + bb2);
            float v1 = a1 * (pb.y + bb2);
            f[2 * j] = v0; f[2 * j + 1] = v1;
            rsum += v0 + v1;
        }
        float4* op = (float4*)(g_xfuse + (size_t)blk * PLANE + row * 56 + cg * 8);
        op[0] = make_float4(f[0], f[1], f[2], f[3]);
        op[1] = make_float4(f[4], f[5], f[6], f[7]);
        partial[row * 7 + cg] = rsum;
    }
    __syncthreads();

    if (tid < 49) {
        const int pr = tid / 7, pc = tid - pr * 7;
        float sm = 0.f;
#pragma unroll
        for (int i = 0; i < 8; i++) sm += partial[(pr * 8 + i) * 7 + pc];
        g_pooled[(b * 49 + tid) * NC + c] = sm * (1.f / 64.f);
    }
}

// ---------------------------------------------------------------------------
// Kernel 2a: hidden layer h = gelu(pw1 @ v + pb1) for all (b, pos).
// ---------------------------------------------------------------------------
__global__ __launch_bounds__(256) void k_dyn_h(const float* __restrict__ pb1) {
    __shared__ float v[10 * 256];

    const int pg = blockIdx.x, b = blockIdx.y, t = threadIdx.x;
    const int base = pg * 10;
    const int nload = (pg == 4) ? 9 : 10;

    for (int i = t; i < nload * 256; i += 256)
        v[i] = g_pooled[(b * 49 + base) * NC + i];
    if (pg == 4) {
        float sm = 0.f;
        for (int p = 0; p < 49; p++) sm += g_pooled[(b * 49 + p) * NC + t];
        v[9 * 256 + t] = sm * (1.f / 49.f);
    }
    __syncthreads();

    const int o = t & 63;
    for (int pl = t >> 6; pl < 10; pl += 4) {
        const float* vr = &v[pl * 256];
        float acc0 = 0.f, acc1 = 0.f;
#pragma unroll 8
        for (int k = 0; k < 256; k += 2) {
            acc0 += g_pw1T[k * 64 + o] * vr[k];
            acc1 += g_pw1T[(k + 1) * 64 + o] * vr[k + 1];
        }
        float x = acc0 + acc1 + pb1[o];
        g_h[(b * 50 + base + pl) * 64 + o] =
            0.5f * x * (1.f + erff(x * 0.70710678118654752f));
    }
}

// ---------------------------------------------------------------------------
// Kernel 2b: logits = h @ pw2 (+pb2), softmax over G, weighted sums.
// ---------------------------------------------------------------------------
__global__ __launch_bounds__(256) void k_dyn2(
    const float* __restrict__ pb2, const float* __restrict__ bias1) {
    __shared__ float hs[50 * 64];

    const int b = blockIdx.y, t = threadIdx.x;
    const int c = blockIdx.x * 32 + (t & 31);
    const int ps = t >> 5;                 // 0..7 pos stripe

    for (int i = t; i < 3200; i += 256) hs[i] = g_h[b * 3200 + i];
    __syncthreads();

    const int np = (ps < 2) ? 7 : 6;       // positions ps, ps+8, ...
    float acc[7][4];
#pragma unroll
    for (int i = 0; i < 7; i++)
#pragma unroll
        for (int g = 0; g < 4; g++) acc[i][g] = 0.f;

#pragma unroll 4
    for (int k = 0; k < 64; k++) {
        const float w0 = g_pw2T[k * 1024 + c];
        const float w1 = g_pw2T[k * 1024 + 256 + c];
        const float w2 = g_pw2T[k * 1024 + 512 + c];
        const float w3 = g_pw2T[k * 1024 + 768 + c];
#pragma unroll
        for (int i = 0; i < 7; i++) {
            if (i < np) {
                const float h = hs[(ps + 8 * i) * 64 + k];
                acc[i][0] += h * w0;
                acc[i][1] += h * w1;
                acc[i][2] += h * w2;
                acc[i][3] += h * w3;
            }
        }
    }

    const float q0 = pb2[c], q1 = pb2[256 + c], q2 = pb2[512 + c], q3 = pb2[768 + c];
#pragma unroll
    for (int i = 0; i < 7; i++) {
        if (i >= np) break;
        const int pos = ps + 8 * i;
        float l0 = acc[i][0] + q0, l1 = acc[i][1] + q1;
        float l2 = acc[i][2] + q2, l3 = acc[i][3] + q3;
        float m = fmaxf(fmaxf(l0, l1), fmaxf(l2, l3));
        float e0 = expf(l0 - m), e1 = expf(l1 - m);
        float e2 = expf(l2 - m), e3 = expf(l3 - m);
        float inv = 1.f / (e0 + e1 + e2 + e3);
        if (pos < 49) {
            const float* wp = &g_w1T[pos * 1024];
            float wv = e0 * wp[c] + e1 * wp[256 + c] + e2 * wp[512 + c] +
                       e3 * wp[768 + c];
            g_wdyn[(b * 49 + pos) * NC + c] = wv * inv;
        } else {
            float bv = e0 * bias1[c] + e1 * bias1[256 + c] +
                       e2 * bias1[512 + c] + e3 * bias1[768 + c];
            g_bdyn[b * NC + c] = bv * inv;
        }
    }
}

// ---------------------------------------------------------------------------
// Kernel 3: dynamic 7x7 depthwise conv + dynamic bias.
// 2-row blocking with ROW-CARRY: loop over ky loads only one new input row;
// weight row w[ky] serves out-row0 (x cur) and out-row1 (x nxt). Smem phases
// per 16 outputs: 294 -> 161. warp = cg, lane = row-pair -> conflict-free
// (banks 2*lane mod 32, distinct within each 16-lane phase). S-accumulators
// for odd taps. 224 threads, 3 blocks/SM (21 warps), no weight-carry regs.
// ---------------------------------------------------------------------------
__global__ __launch_bounds__(224, 3) void k_conv(float* __restrict__ out) {
    __shared__ float s[62 * 66];           // tile, halo 3, stride 66
    __shared__ float2 wsm2[49];            // packed (w,w)
    __shared__ float bsm;

    const int blk = blockIdx.x;
    const int b = blk >> 8, c = blk & 255;
    const int tid = threadIdx.x;

    // halo zeroing: 708 cells over 224 threads
    for (int i = tid; i < 708; i += 224) {
        int r, x;
        if (i < 372) {
            int rr = i / 62; x = i - rr * 62;
            r = (rr < 3) ? rr : 56 + rr;
        } else {
            int j = i - 372;
            r = 3 + j / 6;
            int xs = j - (j / 6) * 6;
            x = (xs < 3) ? xs : 56 + xs;
        }
        s[r * 66 + x] = 0.f;
    }
    {
        const float4* __restrict__ xp4 =
            (const float4*)(g_xfuse + (size_t)blk * PLANE);
        for (int idx = tid; idx < 784; idx += 224) {
            int r = idx / 14, c4 = idx - r * 14;
            float4 v = xp4[idx];
            float* d = &s[(r + 3) * 66 + 3 + c4 * 4];
            d[0] = v.x; d[1] = v.y; d[2] = v.z; d[3] = v.w;
        }
    }
    if (tid < 49) {
        float w = g_wdyn[(b * 49 + tid) * NC + c];
        wsm2[tid] = make_float2(w, w);
    }
    if (tid == 63) bsm = g_bdyn[b * NC + c];
    __syncthreads();

    const int lane = tid & 31;
    const int cg = tid >> 5;               // 0..6
    if (lane < 28) {
        const int r0 = 2 * lane;           // output rows r0, r0+1
        ull a0[4] = {0, 0, 0, 0}, a1[4] = {0, 0, 0, 0};
        ull S0[5] = {0, 0, 0, 0, 0}, S1[5] = {0, 0, 0, 0, 0};
        ull cur[7], nxt[7];
        {
            const float* rp = &s[r0 * 66 + cg * 8];
#pragma unroll
            for (int k = 0; k < 7; k++) cur[k] = *(const ull*)(rp + 2 * k);
        }
#pragma unroll
        for (int ky = 0; ky < 7; ky++) {
            const float* rp = &s[(r0 + ky + 1) * 66 + cg * 8];
#pragma unroll
            for (int k = 0; k < 7; k++) nxt[k] = *(const ull*)(rp + 2 * k);
#pragma unroll
            for (int t = 0; t < 4; t++) {   // even taps kx = 0,2,4,6
                ull w = *(const ull*)&wsm2[ky * 7 + 2 * t];
#pragma unroll
                for (int j = 0; j < 4; j++) {
                    ffma2(a0[j], w, cur[j + t]);
                    ffma2(a1[j], w, nxt[j + t]);
                }
            }
#pragma unroll
            for (int t = 0; t < 3; t++) {   // odd taps kx = 1,3,5 -> S[i]
                ull w = *(const ull*)&wsm2[ky * 7 + 2 * t + 1];
#pragma unroll
                for (int i = 0; i < 5; i++) {
                    ffma2(S0[i], w, cur[i + t]);
                    ffma2(S1[i], w, nxt[i + t]);
                }
            }
#pragma unroll
            for (int k = 0; k < 7; k++) cur[k] = nxt[k];
        }
        const float bv = bsm;
        {
            float2 p0 = u2f2(a0[0]), p1 = u2f2(a0[1]);
            float2 p2 = u2f2(a0[2]), p3 = u2f2(a0[3]);
            float2 q0 = u2f2(S0[0]), q1 = u2f2(S0[1]), q2 = u2f2(S0[2]);
            float2 q3 = u2f2(S0[3]), q4 = u2f2(S0[4]);
            float4* op = (float4*)(out + (size_t)blk * PLANE + r0 * 56 + cg * 8);
            op[0] = make_float4(p0.x + q0.y + bv, p0.y + q1.x + bv,
                                p1.x + q1.y + bv, p1.y + q2.x + bv);
            op[1] = make_float4(p2.x + q2.y + bv, p2.y + q3.x + bv,
                                p3.x + q3.y + bv, p3.y + q4.x + bv);
        }
        {
            float2 p0 = u2f2(a1[0]), p1 = u2f2(a1[1]);
            float2 p2 = u2f2(a1[2]), p3 = u2f2(a1[3]);
            float2 q0 = u2f2(S1[0]), q1 = u2f2(S1[1]), q2 = u2f2(S1[2]);
            float2 q3 = u2f2(S1[3]), q4 = u2f2(S1[4]);
            float4* op = (float4*)(out + (size_t)blk * PLANE + (r0 + 1) * 56 + cg * 8);
            op[0] = make_float4(p0.x + q0.y + bv, p0.y + q1.x + bv,
                                p1.x + q1.y + bv, p1.y + q2.x + bv);
            op[1] = make_float4(p2.x + q2.y + bv, p2.y + q3.x + bv,
                                p3.x + q3.y + bv, p3.y + q4.x + bv);
        }
    }
}

// ---------------------------------------------------------------------------
extern "C" void kernel_launch(void* const* d_in, const int* in_sizes, int n_in,
                              void* d_out, int out_size) {
    const float* x1    = (const float*)d_in[0];
    const float* dw1_w = (const float*)d_in[1];
    const float* dw1_g = (const float*)d_in[2];
    const float* dw1_b = (const float*)d_in[3];
    const float* dw1_m = (const float*)d_in[4];
    const float* dw1_v = (const float*)d_in[5];
    const float* dw2_w = (const float*)d_in[6];
    const float* dw2_g = (const float*)d_in[7];
    const float* dw2_b = (const float*)d_in[8];
    const float* dw2_m = (const float*)d_in[9];
    const float* dw2_v = (const float*)d_in[10];
    const float* weight1 = (const float*)d_in[11];
    const float* bias1   = (const float*)d_in[12];
    const float* pw1 = (const float*)d_in[13];
    const float* pb1 = (const float*)d_in[14];
    const float* pw2 = (const float*)d_in[15];
    const float* pb2 = (const float*)d_in[16];
    float* out = (float*)d_out;

    k_fuse<<<NPLANES + 295, 448>>>(x1, dw1_w, dw1_g, dw1_b, dw1_m, dw1_v,
                                   dw2_w, dw2_g, dw2_b, dw2_m, dw2_v,
                                   pw1, pw2, weight1);
    k_dyn_h<<<dim3(5, NB), 256>>>(pb1);
    k_dyn2<<<dim3(8, NB), 256>>>(pb2, bias1);
    k_conv<<<NPLANES, 224>>>(out);
}

// round 12
// speedup vs baseline: 1.1654x; 1.0626x over previous
#include <cuda_runtime.h>
#include <math.h>

#define NB 16
#define NC 256
#define PLANE 3136
#define NPLANES 4096
typedef unsigned long long ull;

// scratch (static device globals; no allocation)
__device__ float g_xfuse[NPLANES * PLANE];   // 51.4 MB
__device__ float g_pooled[NB * 49 * NC];     // [B][pos][C]
__device__ float g_h[NB * 50 * 64];          // hidden layer (pos 49 = mean)
__device__ float g_wdyn[NB * 49 * NC];       // [B][pos][C]
__device__ float g_bdyn[NB * NC];            // [B][C]
__device__ float g_pw1T[256 * 64];           // [k][o]
__device__ float g_pw2T[64 * 1024];          // [k][oc]
__device__ float g_w1T[49 * 1024];           // [pos][g*C+c]

__device__ __forceinline__ void ffma2(ull& d, ull a, ull b) {
    asm("fma.rn.f32x2 %0, %1, %2, %0;" : "+l"(d) : "l"(a), "l"(b));
}
__device__ __forceinline__ float2 u2f2(ull v) {
    float2 r;
    r.x = __uint_as_float((unsigned)v);
    r.y = __uint_as_float((unsigned)(v >> 32));
    return r;
}

// ---------------------------------------------------------------------------
// Kernel 1: fused dw3x3+BN (x2), relu6 gate, x_fuse, 7x7 block-mean pool.
// warp = column-group, lane = row -> conflict-free LDS.64 (R9-benched form).
// Blocks >= NPLANES instead perform the small weight transposes.
// ---------------------------------------------------------------------------
__global__ __launch_bounds__(448, 3) void k_fuse(
    const float* __restrict__ x1,
    const float* __restrict__ dw1_w, const float* __restrict__ dw1_g,
    const float* __restrict__ dw1_b, const float* __restrict__ dw1_m,
    const float* __restrict__ dw1_v,
    const float* __restrict__ dw2_w, const float* __restrict__ dw2_g,
    const float* __restrict__ dw2_b, const float* __restrict__ dw2_m,
    const float* __restrict__ dw2_v,
    const float* __restrict__ pw1, const float* __restrict__ pw2,
    const float* __restrict__ w1grp) {
    const int tid = threadIdx.x;

    if (blockIdx.x >= NPLANES) {           // transpose side-work
        int i = (blockIdx.x - NPLANES) * 448 + tid;
        if (i < 16384) {                   // pw1 [64,256] -> [256,64]
            int k = i >> 6, o = i & 63;
            g_pw1T[i] = pw1[o * 256 + k];
        } else if (i < 81920) {            // pw2 [1024,64] -> [64,1024]
            int j = i - 16384;
            int k = j >> 10, oc = j & 1023;
            g_pw2T[j] = pw2[oc * 64 + k];
        } else if (i < 132096) {           // weight1 [G*C,49] -> [49,G*C]
            int l = i - 81920;
            int pos = l / 1024, gc = l & 1023;
            g_w1T[l] = w1grp[gc * 49 + pos];
        }
        return;
    }

    __shared__ float s[58 * 66];           // tile, halo 1, stride 66
    __shared__ float2 sw1[9], sw2[9];      // packed (w,w) weights
    __shared__ float partial[392];

    const int blk = blockIdx.x;
    const int b = blk >> 8, c = blk & 255;

    // halo zeroing (rows 0,57 x 0..57; rows 1..56 x in {0,57}): 228 cells
    if (tid < 228) {
        int r, x;
        if (tid < 116) {
            r = (tid < 58) ? 0 : 57;
            x = (tid < 58) ? tid : tid - 58;
        } else {
            int j = tid - 116;
            r = 1 + (j >> 1);
            x = (j & 1) ? 57 : 0;
        }
        s[r * 66 + x] = 0.f;
    }
    {
        const float4* __restrict__ xp4 =
            (const float4*)(x1 + (size_t)blk * PLANE);
        for (int idx = tid; idx < 784; idx += 448) {
            int r = idx / 14, c4 = idx - r * 14;
            float4 v = xp4[idx];
            float* d = &s[(r + 1) * 66 + 1 + c4 * 4];
            d[0] = v.x; d[1] = v.y; d[2] = v.z; d[3] = v.w;
        }
    }
    // BN-folded channel scalars
    const float s1 = dw1_g[c] * rsqrtf(dw1_v[c] + 1e-5f);
    const float s2 = dw2_g[c] * rsqrtf(dw2_v[c] + 1e-5f);
    const float bb1 = dw1_b[c] - dw1_m[c] * s1;
    const float bb2 = dw2_b[c] - dw2_m[c] * s2;
    if (tid < 9) {
        float wa = dw1_w[c * 9 + tid] * s1;
        float wb = dw2_w[c * 9 + tid] * s2;
        sw1[tid] = make_float2(wa, wa);
        sw2[tid] = make_float2(wb, wb);
    }
    __syncthreads();

    const int wp = tid >> 5, lane = tid & 31;
    const int band = (wp >= 7) ? 1 : 0;
    const int cg = wp - band * 7;
    const int row = band * 32 + lane;

    if (row < 56) {
        ull aA[4] = {0, 0, 0, 0}, aB[4] = {0, 0, 0, 0};
#pragma unroll
        for (int ky = 0; ky < 3; ky++) {
            const float* rp = &s[(row + ky) * 66 + cg * 8];
            ull pe[5];
#pragma unroll
            for (int k = 0; k < 5; k++) pe[k] = *(const ull*)(rp + 2 * k);
            ull po[4];
#pragma unroll
            for (int m = 0; m < 4; m++)
                po[m] = (pe[m] >> 32) | (pe[m + 1] << 32);
#pragma unroll
            for (int t = 0; t < 2; t++) {   // kx = 0, 2
                ull wa = *(const ull*)&sw1[ky * 3 + 2 * t];
                ull wb = *(const ull*)&sw2[ky * 3 + 2 * t];
#pragma unroll
                for (int j = 0; j < 4; j++) {
                    ffma2(aA[j], wa, pe[j + t]);
                    ffma2(aB[j], wb, pe[j + t]);
                }
            }
            {                               // kx = 1
                ull wa = *(const ull*)&sw1[ky * 3 + 1];
                ull wb = *(const ull*)&sw2[ky * 3 + 1];
#pragma unroll
                for (int j = 0; j < 4; j++) {
                    ffma2(aA[j], wa, po[j]);
                    ffma2(aB[j], wb, po[j]);
                }
            }
        }
        float f[8];
        float rsum = 0.f;
#pragma unroll
        for (int j = 0; j < 4; j++) {
            float2 pa = u2f2(aA[j]), pb = u2f2(aB[j]);
            float a0 = fminf(fmaxf(pa.x + bb1, 0.f), 6.f);
            float a1 = fminf(fmaxf(pa.y + bb1, 0.f), 6.f);
            float v0 = a0 * (pb.x + bb2);
            float v1 = a1 * (pb.y + bb2);
            f[2 * j] = v0; f[2 * j + 1] = v1;
            rsum += v0 + v1;
        }
        float4* op = (float4*)(g_xfuse + (size_t)blk * PLANE + row * 56 + cg * 8);
        op[0] = make_float4(f[0], f[1], f[2], f[3]);
        op[1] = make_float4(f[4], f[5], f[6], f[7]);
        partial[row * 7 + cg] = rsum;
    }
    __syncthreads();

    if (tid < 49) {
        const int pr = tid / 7, pc = tid - pr * 7;
        float sm = 0.f;
#pragma unroll
        for (int i = 0; i < 8; i++) sm += partial[(pr * 8 + i) * 7 + pc];
        g_pooled[(b * 49 + tid) * NC + c] = sm * (1.f / 64.f);
    }
}

// ---------------------------------------------------------------------------
// Kernel 2a: hidden layer h = gelu(pw1 @ v + pb1) for all (b, pos).
// ---------------------------------------------------------------------------
__global__ __launch_bounds__(256) void k_dyn_h(const float* __restrict__ pb1) {
    __shared__ float v[10 * 256];

    const int pg = blockIdx.x, b = blockIdx.y, t = threadIdx.x;
    const int base = pg * 10;
    const int nload = (pg == 4) ? 9 : 10;

    for (int i = t; i < nload * 256; i += 256)
        v[i] = g_pooled[(b * 49 + base) * NC + i];
    if (pg == 4) {
        float sm = 0.f;
        for (int p = 0; p < 49; p++) sm += g_pooled[(b * 49 + p) * NC + t];
        v[9 * 256 + t] = sm * (1.f / 49.f);
    }
    __syncthreads();

    const int o = t & 63;
    for (int pl = t >> 6; pl < 10; pl += 4) {
        const float* vr = &v[pl * 256];
        float acc0 = 0.f, acc1 = 0.f;
#pragma unroll 8
        for (int k = 0; k < 256; k += 2) {
            acc0 += g_pw1T[k * 64 + o] * vr[k];
            acc1 += g_pw1T[(k + 1) * 64 + o] * vr[k + 1];
        }
        float x = acc0 + acc1 + pb1[o];
        g_h[(b * 50 + base + pl) * 64 + o] =
            0.5f * x * (1.f + erff(x * 0.70710678118654752f));
    }
}

// ---------------------------------------------------------------------------
// Kernel 2b: logits = h @ pw2 (+pb2), softmax over G, weighted sums.
// ---------------------------------------------------------------------------
__global__ __launch_bounds__(256) void k_dyn2(
    const float* __restrict__ pb2, const float* __restrict__ bias1) {
    __shared__ float hs[50 * 64];

    const int b = blockIdx.y, t = threadIdx.x;
    const int c = blockIdx.x * 32 + (t & 31);
    const int ps = t >> 5;                 // 0..7 pos stripe

    for (int i = t; i < 3200; i += 256) hs[i] = g_h[b * 3200 + i];
    __syncthreads();

    const int np = (ps < 2) ? 7 : 6;       // positions ps, ps+8, ...
    float acc[7][4];
#pragma unroll
    for (int i = 0; i < 7; i++)
#pragma unroll
        for (int g = 0; g < 4; g++) acc[i][g] = 0.f;

#pragma unroll 4
    for (int k = 0; k < 64; k++) {
        const float w0 = g_pw2T[k * 1024 + c];
        const float w1 = g_pw2T[k * 1024 + 256 + c];
        const float w2 = g_pw2T[k * 1024 + 512 + c];
        const float w3 = g_pw2T[k * 1024 + 768 + c];
#pragma unroll
        for (int i = 0; i < 7; i++) {
            if (i < np) {
                const float h = hs[(ps + 8 * i) * 64 + k];
                acc[i][0] += h * w0;
                acc[i][1] += h * w1;
                acc[i][2] += h * w2;
                acc[i][3] += h * w3;
            }
        }
    }

    const float q0 = pb2[c], q1 = pb2[256 + c], q2 = pb2[512 + c], q3 = pb2[768 + c];
#pragma unroll
    for (int i = 0; i < 7; i++) {
        if (i >= np) break;
        const int pos = ps + 8 * i;
        float l0 = acc[i][0] + q0, l1 = acc[i][1] + q1;
        float l2 = acc[i][2] + q2, l3 = acc[i][3] + q3;
        float m = fmaxf(fmaxf(l0, l1), fmaxf(l2, l3));
        float e0 = expf(l0 - m), e1 = expf(l1 - m);
        float e2 = expf(l2 - m), e3 = expf(l3 - m);
        float inv = 1.f / (e0 + e1 + e2 + e3);
        if (pos < 49) {
            const float* wp = &g_w1T[pos * 1024];
            float wv = e0 * wp[c] + e1 * wp[256 + c] + e2 * wp[512 + c] +
                       e3 * wp[768 + c];
            g_wdyn[(b * 49 + pos) * NC + c] = wv * inv;
        } else {
            float bv = e0 * bias1[c] + e1 * bias1[256 + c] +
                       e2 * bias1[512 + c] + e3 * bias1[768 + c];
            g_bdyn[b * NC + c] = bv * inv;
        }
    }
}

// ---------------------------------------------------------------------------
// Kernel 3: dynamic 7x7 depthwise conv + dynamic bias.
// R9 mainloop (S-accumulators, conflict-free lane=row LDS.64) on HALF-PLANE
// blocks: 224 threads (7 warps), 28 output rows, tile 34x66 (~9KB). Same
// 28-warp/SM ceiling as R9 but 4 small blocks instead of 2 big ones ->
// finer interleave, cheaper barriers, shorter prologue. launch_bounds(224,6)
// pins the ptxas budget at 48 regs (= R9 pressure); HW caps at 4 blocks.
// ---------------------------------------------------------------------------
__global__ __launch_bounds__(224, 6) void k_conv(float* __restrict__ out) {
    __shared__ float s[34 * 66];           // half tile, halo 3, stride 66
    __shared__ float2 wsm2[49];            // packed (w,w)
    __shared__ float bsm;

    const int bp = blockIdx.x >> 1;        // plane
    const int half = blockIdx.x & 1;       // 0: rows 0..27, 1: rows 28..55
    const int b = bp >> 8, c = bp & 255;
    const int base = half * 28;
    const int tid = threadIdx.x;

    // column-halo zeroing: cols {0,1,2,59,60,61} x 34 rows = 204 cells
    if (tid < 204) {
        int r = tid / 6, xs = tid - r * 6;
        int x = (xs < 3) ? xs : 56 + xs;
        s[r * 66 + x] = 0.f;
    }
    {
        const float4* __restrict__ xp4 =
            (const float4*)(g_xfuse + (size_t)bp * PLANE);
        for (int idx = tid; idx < 476; idx += 224) {   // 34 rows x 14 f4
            int r = idx / 14, c4 = idx - r * 14;
            int gr = base - 3 + r;
            float4 v = make_float4(0.f, 0.f, 0.f, 0.f);
            if ((unsigned)gr < 56u) v = xp4[gr * 14 + c4];
            float* d = &s[r * 66 + 3 + c4 * 4];
            d[0] = v.x; d[1] = v.y; d[2] = v.z; d[3] = v.w;
        }
    }
    if (tid < 49) {
        float w = g_wdyn[(b * 49 + tid) * NC + c];
        wsm2[tid] = make_float2(w, w);
    }
    if (tid == 63) bsm = g_bdyn[b * NC + c];
    __syncthreads();

    const int lane = tid & 31;
    const int cg = tid >> 5;               // 0..6
    if (lane < 28) {
        const int row = base + lane;       // output row (global)
        ull acc[4] = {0, 0, 0, 0};
        ull S[5] = {0, 0, 0, 0, 0};
#pragma unroll
        for (int ky = 0; ky < 7; ky++) {
            const float* rp = &s[(lane + ky) * 66 + cg * 8];
            ull pe[7];
#pragma unroll
            for (int k = 0; k < 7; k++) pe[k] = *(const ull*)(rp + 2 * k);
#pragma unroll
            for (int t = 0; t < 4; t++) {   // even taps kx = 0,2,4,6
                ull w = *(const ull*)&wsm2[ky * 7 + 2 * t];
#pragma unroll
                for (int j = 0; j < 4; j++) ffma2(acc[j], w, pe[j + t]);
            }
#pragma unroll
            for (int t = 0; t < 3; t++) {   // odd taps kx = 1,3,5 -> S[i]
                ull w = *(const ull*)&wsm2[ky * 7 + 2 * t + 1];
#pragma unroll
                for (int i = 0; i < 5; i++) ffma2(S[i], w, pe[i + t]);
            }
        }
        const float bv = bsm;
        float2 a0 = u2f2(acc[0]), a1 = u2f2(acc[1]);
        float2 a2 = u2f2(acc[2]), a3 = u2f2(acc[3]);
        float2 s0 = u2f2(S[0]), s1 = u2f2(S[1]), s2 = u2f2(S[2]);
        float2 s3 = u2f2(S[3]), s4 = u2f2(S[4]);
        float4* op = (float4*)(out + (size_t)bp * PLANE + row * 56 + cg * 8);
        op[0] = make_float4(a0.x + s0.y + bv, a0.y + s1.x + bv,
                            a1.x + s1.y + bv, a1.y + s2.x + bv);
        op[1] = make_float4(a2.x + s2.y + bv, a2.y + s3.x + bv,
                            a3.x + s3.y + bv, a3.y + s4.x + bv);
    }
}

// ---------------------------------------------------------------------------
extern "C" void kernel_launch(void* const* d_in, const int* in_sizes, int n_in,
                              void* d_out, int out_size) {
    const float* x1    = (const float*)d_in[0];
    const float* dw1_w = (const float*)d_in[1];
    const float* dw1_g = (const float*)d_in[2];
    const float* dw1_b = (const float*)d_in[3];
    const float* dw1_m = (const float*)d_in[4];
    const float* dw1_v = (const float*)d_in[5];
    const float* dw2_w = (const float*)d_in[6];
    const float* dw2_g = (const float*)d_in[7];
    const float* dw2_b = (const float*)d_in[8];
    const float* dw2_m = (const float*)d_in[9];
    const float* dw2_v = (const float*)d_in[10];
    const float* weight1 = (const float*)d_in[11];
    const float* bias1   = (const float*)d_in[12];
    const float* pw1 = (const float*)d_in[13];
    const float* pb1 = (const float*)d_in[14];
    const float* pw2 = (const float*)d_in[15];
    const float* pb2 = (const float*)d_in[16];
    float* out = (float*)d_out;

    k_fuse<<<NPLANES + 295, 448>>>(x1, dw1_w, dw1_g, dw1_b, dw1_m, dw1_v,
                                   dw2_w, dw2_g, dw2_b, dw2_m, dw2_v,
                                   pw1, pw2, weight1);
    k_dyn_h<<<dim3(5, NB), 256>>>(pb1);
    k_dyn2<<<dim3(8, NB), 256>>>(pb2, bias1);
    k_conv<<<NPLANES * 2, 224>>>(out);
}

// round 14
// speedup vs baseline: 1.1660x; 1.0005x over previous
#include <cuda_runtime.h>
#include <math.h>

#define NB 16
#define NC 256
#define PLANE 3136
#define NPLANES 4096
typedef unsigned long long ull;

// scratch (static device globals; no allocation)
__device__ float g_xfuse[NPLANES * PLANE];   // 51.4 MB
__device__ float g_pool2[NB * 2 * 28 * NC];  // partial pools [b][half][bin][c]
__device__ float g_h[NB * 50 * 64];          // hidden layer (pos 49 = mean)
__device__ float g_wdyn[NB * 49 * NC];       // [B][pos][C]
__device__ float g_bdyn[NB * NC];            // [B][C]
__device__ float g_pw1T[256 * 64];           // [k][o]
__device__ float g_pw2T[64 * 1024];          // [k][oc]
__device__ float g_w1T[49 * 1024];           // [pos][g*C+c]

__device__ __forceinline__ void ffma2(ull& d, ull a, ull b) {
    asm("fma.rn.f32x2 %0, %1, %2, %0;" : "+l"(d) : "l"(a), "l"(b));
}
__device__ __forceinline__ float2 u2f2(ull v) {
    float2 r;
    r.x = __uint_as_float((unsigned)v);
    r.y = __uint_as_float((unsigned)(v >> 32));
    return r;
}

// ---------------------------------------------------------------------------
// Kernel 1: fused dw3x3+BN (x2), relu6 gate, x_fuse, partial 7x7 pooling.
// HALF-PLANE blocks (224 thr, 28 rows, tile 30x66), lane = row (conflict-
// free LDS.64), po-recombine mainloop (R9-proven). Pool partials go to
// g_pool2[b][half][4x7 bins][c]; k_dyn_h combines the split pool row 3.
// Blocks >= 2*NPLANES perform the small weight transposes.
// ---------------------------------------------------------------------------
__global__ __launch_bounds__(224, 6) void k_fuse(
    const float* __restrict__ x1,
    const float* __restrict__ dw1_w, const float* __restrict__ dw1_g,
    const float* __restrict__ dw1_b, const float* __restrict__ dw1_m,
    const float* __restrict__ dw1_v,
    const float* __restrict__ dw2_w, const float* __restrict__ dw2_g,
    const float* __restrict__ dw2_b, const float* __restrict__ dw2_m,
    const float* __restrict__ dw2_v,
    const float* __restrict__ pw1, const float* __restrict__ pw2,
    const float* __restrict__ w1grp) {
    const int tid = threadIdx.x;

    if (blockIdx.x >= 2 * NPLANES) {       // transpose side-work
        int i = (blockIdx.x - 2 * NPLANES) * 224 + tid;
        if (i < 16384) {                   // pw1 [64,256] -> [256,64]
            int k = i >> 6, o = i & 63;
            g_pw1T[i] = pw1[o * 256 + k];
        } else if (i < 81920) {            // pw2 [1024,64] -> [64,1024]
            int j = i - 16384;
            int k = j >> 10, oc = j & 1023;
            g_pw2T[j] = pw2[oc * 64 + k];
        } else if (i < 132096) {           // weight1 [G*C,49] -> [49,G*C]
            int l = i - 81920;
            int pos = l / 1024, gc = l & 1023;
            g_w1T[l] = w1grp[gc * 49 + pos];
        }
        return;
    }

    __shared__ float s[30 * 66];           // half tile, halo 1, stride 66
    __shared__ float2 sw1[9], sw2[9];      // packed (w,w) weights
    __shared__ float partial[196];

    const int bp = blockIdx.x >> 1;
    const int half = blockIdx.x & 1;       // 0: rows 0..27, 1: rows 28..55
    const int b = bp >> 8, c = bp & 255;
    const int base = half * 28;

    // column halo: x in {0,57} for all 30 tile rows
    if (tid < 60) {
        int r = tid >> 1, x = (tid & 1) ? 57 : 0;
        s[r * 66 + x] = 0.f;
    }
    {
        const float4* __restrict__ xp4 =
            (const float4*)(x1 + (size_t)bp * PLANE);
        for (int idx = tid; idx < 420; idx += 224) {   // 30 rows x 14 f4
            int r = idx / 14, c4 = idx - r * 14;
            int gr = base - 1 + r;
            float4 v = make_float4(0.f, 0.f, 0.f, 0.f);
            if ((unsigned)gr < 56u) v = xp4[gr * 14 + c4];
            float* d = &s[r * 66 + 1 + c4 * 4];
            d[0] = v.x; d[1] = v.y; d[2] = v.z; d[3] = v.w;
        }
    }
    // BN-folded channel scalars
    const float s1 = dw1_g[c] * rsqrtf(dw1_v[c] + 1e-5f);
    const float s2 = dw2_g[c] * rsqrtf(dw2_v[c] + 1e-5f);
    const float bb1 = dw1_b[c] - dw1_m[c] * s1;
    const float bb2 = dw2_b[c] - dw2_m[c] * s2;
    if (tid < 9) {
        float wa = dw1_w[c * 9 + tid] * s1;
        float wb = dw2_w[c * 9 + tid] * s2;
        sw1[tid] = make_float2(wa, wa);
        sw2[tid] = make_float2(wb, wb);
    }
    __syncthreads();

    const int lane = tid & 31;
    const int cg = tid >> 5;               // 0..6
    if (lane < 28) {
        ull aA[4] = {0, 0, 0, 0}, aB[4] = {0, 0, 0, 0};
#pragma unroll
        for (int ky = 0; ky < 3; ky++) {
            const float* rp = &s[(lane + ky) * 66 + cg * 8];
            ull pe[5];
#pragma unroll
            for (int k = 0; k < 5; k++) pe[k] = *(const ull*)(rp + 2 * k);
            ull po[4];
#pragma unroll
            for (int m = 0; m < 4; m++)
                po[m] = (pe[m] >> 32) | (pe[m + 1] << 32);
#pragma unroll
            for (int t = 0; t < 2; t++) {   // kx = 0, 2
                ull wa = *(const ull*)&sw1[ky * 3 + 2 * t];
                ull wb = *(const ull*)&sw2[ky * 3 + 2 * t];
#pragma unroll
                for (int j = 0; j < 4; j++) {
                    ffma2(aA[j], wa, pe[j + t]);
                    ffma2(aB[j], wb, pe[j + t]);
                }
            }
            {                               // kx = 1
                ull wa = *(const ull*)&sw1[ky * 3 + 1];
                ull wb = *(const ull*)&sw2[ky * 3 + 1];
#pragma unroll
                for (int j = 0; j < 4; j++) {
                    ffma2(aA[j], wa, po[j]);
                    ffma2(aB[j], wb, po[j]);
                }
            }
        }
        float f[8];
        float rsum = 0.f;
#pragma unroll
        for (int j = 0; j < 4; j++) {
            float2 pa = u2f2(aA[j]), pb = u2f2(aB[j]);
            float a0 = fminf(fmaxf(pa.x + bb1, 0.f), 6.f);
            float a1 = fminf(fmaxf(pa.y + bb1, 0.f), 6.f);
            float v0 = a0 * (pb.x + bb2);
            float v1 = a1 * (pb.y + bb2);
            f[2 * j] = v0; f[2 * j + 1] = v1;
            rsum += v0 + v1;
        }
        const int row = base + lane;
        float4* op = (float4*)(g_xfuse + (size_t)bp * PLANE + row * 56 + cg * 8);
        op[0] = make_float4(f[0], f[1], f[2], f[3]);
        op[1] = make_float4(f[4], f[5], f[6], f[7]);
        partial[lane * 7 + cg] = rsum;
    }
    __syncthreads();

    // partial pooling: 28 bins (4 local pool rows x 7 cols)
    if (tid < 28) {
        const int p = tid / 7, pc = tid - p * 7;
        int start, cnt;
        if (half == 0) { start = p * 8;                cnt = (p < 3) ? 8 : 4; }
        else           { start = (p == 0) ? 0 : p * 8 - 4; cnt = (p == 0) ? 4 : 8; }
        float sm = 0.f;
        for (int i = 0; i < cnt; i++) sm += partial[(start + i) * 7 + pc];
        g_pool2[((b * 2 + half) * 28 + tid) * NC + c] = sm;
    }
}

// ---------------------------------------------------------------------------
// Kernel 2a: hidden layer h = gelu(pw1 @ v + pb1) for all (b, pos).
// Combines the two pool halves (pool row 3 spans both).
// ---------------------------------------------------------------------------
__global__ __launch_bounds__(256) void k_dyn_h(const float* __restrict__ pb1) {
    __shared__ float v[10 * 256];

    const int pg = blockIdx.x, b = blockIdx.y, t = threadIdx.x;
    const int base = pg * 10;
    const int nload = (pg == 4) ? 9 : 10;

    for (int i = t; i < nload * 256; i += 256) {
        int pos = base + i / 256;
        int cc = i & 255;
        int pr = pos / 7, pc = pos - pr * 7;
        float val = 0.f;
        if (pr <= 3) val += g_pool2[((b * 2 + 0) * 28 + pr * 7 + pc) * NC + cc];
        if (pr >= 3) val += g_pool2[((b * 2 + 1) * 28 + (pr - 3) * 7 + pc) * NC + cc];
        v[i] = val * (1.f / 64.f);
    }
    if (pg == 4) {
        float sm = 0.f;
        for (int j = 0; j < 28; j++)
            sm += g_pool2[((b * 2 + 0) * 28 + j) * NC + t] +
                  g_pool2[((b * 2 + 1) * 28 + j) * NC + t];
        v[9 * 256 + t] = sm * (1.f / (64.f * 49.f));
    }
    __syncthreads();

    const int o = t & 63;
    for (int pl = t >> 6; pl < 10; pl += 4) {
        const float* vr = &v[pl * 256];
        float acc0 = 0.f, acc1 = 0.f;
#pragma unroll 8
        for (int k = 0; k < 256; k += 2) {
            acc0 += g_pw1T[k * 64 + o] * vr[k];
            acc1 += g_pw1T[(k + 1) * 64 + o] * vr[k + 1];
        }
        float x = acc0 + acc1 + pb1[o];
        g_h[(b * 50 + base + pl) * 64 + o] =
            0.5f * x * (1.f + erff(x * 0.70710678118654752f));
    }
}

// ---------------------------------------------------------------------------
// Kernel 2b: logits = h @ pw2 (+pb2), softmax over G, weighted sums.
// ---------------------------------------------------------------------------
__global__ __launch_bounds__(256) void k_dyn2(
    const float* __restrict__ pb2, const float* __restrict__ bias1) {
    __shared__ float hs[50 * 64];

    const int b = blockIdx.y, t = threadIdx.x;
    const int c = blockIdx.x * 32 + (t & 31);
    const int ps = t >> 5;                 // 0..7 pos stripe

    for (int i = t; i < 3200; i += 256) hs[i] = g_h[b * 3200 + i];
    __syncthreads();

    const int np = (ps < 2) ? 7 : 6;       // positions ps, ps+8, ...
    float acc[7][4];
#pragma unroll
    for (int i = 0; i < 7; i++)
#pragma unroll
        for (int g = 0; g < 4; g++) acc[i][g] = 0.f;

#pragma unroll 4
    for (int k = 0; k < 64; k++) {
        const float w0 = g_pw2T[k * 1024 + c];
        const float w1 = g_pw2T[k * 1024 + 256 + c];
        const float w2 = g_pw2T[k * 1024 + 512 + c];
        const float w3 = g_pw2T[k * 1024 + 768 + c];
#pragma unroll
        for (int i = 0; i < 7; i++) {
            if (i < np) {
                const float h = hs[(ps + 8 * i) * 64 + k];
                acc[i][0] += h * w0;
                acc[i][1] += h * w1;
                acc[i][2] += h * w2;
                acc[i][3] += h * w3;
            }
        }
    }

    const float q0 = pb2[c], q1 = pb2[256 + c], q2 = pb2[512 + c], q3 = pb2[768 + c];
#pragma unroll
    for (int i = 0; i < 7; i++) {
        if (i >= np) break;
        const int pos = ps + 8 * i;
        float l0 = acc[i][0] + q0, l1 = acc[i][1] + q1;
        float l2 = acc[i][2] + q2, l3 = acc[i][3] + q3;
        float m = fmaxf(fmaxf(l0, l1), fmaxf(l2, l3));
        float e0 = expf(l0 - m), e1 = expf(l1 - m);
        float e2 = expf(l2 - m), e3 = expf(l3 - m);
        float inv = 1.f / (e0 + e1 + e2 + e3);
        if (pos < 49) {
            const float* wp = &g_w1T[pos * 1024];
            float wv = e0 * wp[c] + e1 * wp[256 + c] + e2 * wp[512 + c] +
                       e3 * wp[768 + c];
            g_wdyn[(b * 49 + pos) * NC + c] = wv * inv;
        } else {
            float bv = e0 * bias1[c] + e1 * bias1[256 + c] +
                       e2 * bias1[512 + c] + e3 * bias1[768 + c];
            g_bdyn[b * NC + c] = bv * inv;
        }
    }
}

// ---------------------------------------------------------------------------
// Kernel 3: dynamic 7x7 depthwise conv + dynamic bias. R12 half-plane form
// + VECTORIZED weight loads: wsm2 padded to stride 8 (64B/ky, 16B-aligned)
// so each ky fetches weights as 3x LDS.128 + 1x LDS.64 (4 wavefronts vs 7).
// ---------------------------------------------------------------------------
__global__ __launch_bounds__(224, 6) void k_conv(float* __restrict__ out) {
    __shared__ float s[34 * 66];           // half tile, halo 3, stride 66
    __shared__ __align__(16) float2 wsm2[56];  // (w,w), stride 8 per ky row
    __shared__ float bsm;

    const int bp = blockIdx.x >> 1;        // plane
    const int half = blockIdx.x & 1;       // 0: rows 0..27, 1: rows 28..55
    const int b = bp >> 8, c = bp & 255;
    const int base = half * 28;
    const int tid = threadIdx.x;

    // column-halo zeroing: cols {0,1,2,59,60,61} x 34 rows = 204 cells
    if (tid < 204) {
        int r = tid / 6, xs = tid - r * 6;
        int x = (xs < 3) ? xs : 56 + xs;
        s[r * 66 + x] = 0.f;
    }
    {
        const float4* __restrict__ xp4 =
            (const float4*)(g_xfuse + (size_t)bp * PLANE);
        for (int idx = tid; idx < 476; idx += 224) {   // 34 rows x 14 f4
            int r = idx / 14, c4 = idx - r * 14;
            int gr = base - 3 + r;
            float4 v = make_float4(0.f, 0.f, 0.f, 0.f);
            if ((unsigned)gr < 56u) v = xp4[gr * 14 + c4];
            float* d = &s[r * 66 + 3 + c4 * 4];
            d[0] = v.x; d[1] = v.y; d[2] = v.z; d[3] = v.w;
        }
    }
    if (tid < 49) {
        int ky = tid / 7, kx = tid - ky * 7;
        float w = g_wdyn[(b * 49 + tid) * NC + c];
        wsm2[ky * 8 + kx] = make_float2(w, w);
    }
    if (tid == 63) bsm = g_bdyn[b * NC + c];
    __syncthreads();

    const int lane = tid & 31;
    const int cg = tid >> 5;               // 0..6
    if (lane < 28) {
        const int row = base + lane;       // output row (global)
        ull acc[4] = {0, 0, 0, 0};
        ull S[5] = {0, 0, 0, 0, 0};
#pragma unroll
        for (int ky = 0; ky < 7; ky++) {
            const float* rp = &s[(lane + ky) * 66 + cg * 8];
            ull pe[7];
#pragma unroll
            for (int k = 0; k < 7; k++) pe[k] = *(const ull*)(rp + 2 * k);
            // vectorized weight fetch: kx pairs (0,1) (2,3) (4,5) + 6
            ulonglong2 wq0 = *(const ulonglong2*)&wsm2[ky * 8 + 0];
            ulonglong2 wq1 = *(const ulonglong2*)&wsm2[ky * 8 + 2];
            ulonglong2 wq2 = *(const ulonglong2*)&wsm2[ky * 8 + 4];
            ull w6 = *(const ull*)&wsm2[ky * 8 + 6];
            ull we[4] = {wq0.x, wq1.x, wq2.x, w6};    // kx = 0,2,4,6
            ull wo[3] = {wq0.y, wq1.y, wq2.y};        // kx = 1,3,5
#pragma unroll
            for (int t = 0; t < 4; t++)
#pragma unroll
                for (int j = 0; j < 4; j++) ffma2(acc[j], we[t], pe[j + t]);
#pragma unroll
            for (int t = 0; t < 3; t++)
#pragma unroll
                for (int i = 0; i < 5; i++) ffma2(S[i], wo[t], pe[i + t]);
        }
        const float bv = bsm;
        float2 a0 = u2f2(acc[0]), a1 = u2f2(acc[1]);
        float2 a2 = u2f2(acc[2]), a3 = u2f2(acc[3]);
        float2 s0 = u2f2(S[0]), s1 = u2f2(S[1]), s2 = u2f2(S[2]);
        float2 s3 = u2f2(S[3]), s4 = u2f2(S[4]);
        float4* op = (float4*)(out + (size_t)bp * PLANE + row * 56 + cg * 8);
        op[0] = make_float4(a0.x + s0.y + bv, a0.y + s1.x + bv,
                            a1.x + s1.y + bv, a1.y + s2.x + bv);
        op[1] = make_float4(a2.x + s2.y + bv, a2.y + s3.x + bv,
                            a3.x + s3.y + bv, a3.y + s4.x + bv);
    }
}

// ---------------------------------------------------------------------------
extern "C" void kernel_launch(void* const* d_in, const int* in_sizes, int n_in,
                              void* d_out, int out_size) {
    const float* x1    = (const float*)d_in[0];
    const float* dw1_w = (const float*)d_in[1];
    const float* dw1_g = (const float*)d_in[2];
    const float* dw1_b = (const float*)d_in[3];
    const float* dw1_m = (const float*)d_in[4];
    const float* dw1_v = (const float*)d_in[5];
    const float* dw2_w = (const float*)d_in[6];
    const float* dw2_g = (const float*)d_in[7];
    const float* dw2_b = (const float*)d_in[8];
    const float* dw2_m = (const float*)d_in[9];
    const float* dw2_v = (const float*)d_in[10];
    const float* weight1 = (const float*)d_in[11];
    const float* bias1   = (const float*)d_in[12];
    const float* pw1 = (const float*)d_in[13];
    const float* pb1 = (const float*)d_in[14];
    const float* pw2 = (const float*)d_in[15];
    const float* pb2 = (const float*)d_in[16];
    float* out = (float*)d_out;

    k_fuse<<<NPLANES * 2 + 590, 224>>>(x1, dw1_w, dw1_g, dw1_b, dw1_m, dw1_v,
                                       dw2_w, dw2_g, dw2_b, dw2_m, dw2_v,
                                       pw1, pw2, weight1);
    k_dyn_h<<<dim3(5, NB), 256>>>(pb1);
    k_dyn2<<<dim3(8, NB), 256>>>(pb2, bias1);
    k_conv<<<NPLANES * 2, 224>>>(out);
}